// round 5
// baseline (speedup 1.0000x reference)
#include <cuda_runtime.h>
#include <cuda_bf16.h>
#include <cstdint>

// ---------------- problem constants ----------------
#define T_TOK   8192
#define D_MODEL 1024
#define D_COND  256
#define D_IN    1280      // D_MODEL + D_COND
#define D_FF    4096
#define NEXP    8
#define TOPK    2
#define CAP     2560      // int(1.25 * 2 * 8192 / 8)
#define TKA     (T_TOK*TOPK)

// ---------------- device scratch (static, no runtime allocation) ----------------
__device__ int   g_expert[TKA];
__device__ float g_weight[TKA];
__device__ int   g_slot[TKA];
__device__ int   g_route[NEXP*CAP];
__device__ int   g_cnt[NEXP];
__device__ float g_Hs[(size_t)T_TOK * D_FF];          // shared-expert hidden
__device__ float g_He[(size_t)NEXP * CAP * D_FF];     // routed-expert hidden
__device__ float g_Y [(size_t)NEXP * CAP * D_MODEL];  // routed-expert output

// ---------------- helpers ----------------
__device__ __forceinline__ unsigned f2tf(float f) {
    unsigned u;
    asm("cvt.rna.tf32.f32 %0, %1;" : "=r"(u) : "f"(f));
    return u;
}
__device__ __forceinline__ void cp16(void* dst_smem, const void* src_gmem) {
    unsigned sa = (unsigned)__cvta_generic_to_shared(dst_smem);
    asm volatile("cp.async.cg.shared.global [%0], [%1], 16;" :: "r"(sa), "l"(src_gmem));
}
__device__ __forceinline__ float gelu_f(float v) {
    // jax.nn.gelu default (approximate=True, tanh form)
    float u = 0.7978845608028654f * (v + 0.044715f * v * v * v);
    return 0.5f * v * (1.0f + tanhf(u));
}

// ---------------- 1) router: scores -> softmax -> top2 -> normalized weights ----------------
__global__ __launch_bounds__(256) void router_kernel(const float* __restrict__ x,
                                                     const float* __restrict__ Wr) {
    __shared__ float sWr[D_MODEL * NEXP];  // 32 KB
    const int tid = threadIdx.x;
    for (int i = tid; i < D_MODEL * NEXP; i += 256) sWr[i] = Wr[i];
    __syncthreads();

    const int warp = tid >> 5, lane = tid & 31;
    const int t = blockIdx.x * 8 + warp;
    const float* xr = x + (size_t)t * D_MODEL;

    float acc[NEXP];
#pragma unroll
    for (int e = 0; e < NEXP; e++) acc[e] = 0.f;

    for (int j = lane; j < D_MODEL; j += 32) {
        float xv = xr[j];
        const float* wrow = sWr + j * NEXP;
#pragma unroll
        for (int e = 0; e < NEXP; e++) acc[e] += xv * wrow[e];
    }
#pragma unroll
    for (int e = 0; e < NEXP; e++)
#pragma unroll
        for (int o = 16; o > 0; o >>= 1) acc[e] += __shfl_xor_sync(0xffffffffu, acc[e], o);

    if (lane == 0) {
        float mx = acc[0];
#pragma unroll
        for (int e = 1; e < NEXP; e++) mx = fmaxf(mx, acc[e]);
        float p[NEXP];
#pragma unroll
        for (int e = 0; e < NEXP; e++) p[e] = expf(acc[e] - mx);
        // top-1 (lowest index on tie), then top-2
        int i1 = 0; float v1 = p[0];
#pragma unroll
        for (int e = 1; e < NEXP; e++) if (p[e] > v1) { v1 = p[e]; i1 = e; }
        int i2 = -1; float v2 = -1.f;
#pragma unroll
        for (int e = 0; e < NEXP; e++) if (e != i1 && p[e] > v2) { v2 = p[e]; i2 = e; }
        float inv = 1.f / (v1 + v2);   // softmax denom cancels in normalization
        g_expert[2 * t]     = i1;  g_weight[2 * t]     = v1 * inv;
        g_expert[2 * t + 1] = i2;  g_weight[2 * t + 1] = v2 * inv;
    }
}

// ---------------- 2) binning: deterministic stable per-expert ranks ----------------
__global__ __launch_bounds__(512) void binning_kernel() {
    __shared__ int scnt[512 * NEXP];   // 16 KB
    const int tid = threadIdx.x;

    // zero routing table so any slot read is safe
    for (int i = tid; i < NEXP * CAP; i += 512) g_route[i] = 0;

    const int base = tid * (TKA / 512);   // 32 assignments per thread
    int loc[NEXP];
#pragma unroll
    for (int e = 0; e < NEXP; e++) loc[e] = 0;
    for (int i = 0; i < TKA / 512; i++) loc[g_expert[base + i]]++;
#pragma unroll
    for (int e = 0; e < NEXP; e++) scnt[tid * NEXP + e] = loc[e];
    __syncthreads();

    if (tid < NEXP) {
        int run = 0;
        for (int i = 0; i < 512; i++) {
            int v = scnt[i * NEXP + tid];
            scnt[i * NEXP + tid] = run;
            run += v;
        }
        g_cnt[tid] = min(run, CAP);
    }
    __syncthreads();

    int offs[NEXP];
#pragma unroll
    for (int e = 0; e < NEXP; e++) offs[e] = scnt[tid * NEXP + e];
    for (int i = 0; i < TKA / 512; i++) {
        int a = base + i;
        int e = g_expert[a];
        int pos = offs[e]++;
        if (pos < CAP) {
            int slot = e * CAP + pos;
            g_route[slot] = a >> 1;   // source token
            g_slot[a] = slot;
        } else {
            g_slot[a] = -1;           // capacity drop
        }
    }
}

// ---------------- 3) tiled tf32 GEMM (mma.sync m16n8k8, cp.async double-buffer) ----------------
// MODE 0: shared L1  : H = gelu([x|cond] @ W1s)          M=T_TOK, K=1280, N=4096
// MODE 1: expert L1  : He = gelu(gather([x|cond]) @ W1e) M=CAP/e, K=1280, N=4096
// MODE 2: shared L2  : out = mask * (Hs @ W2s) / 3       M=T_TOK, K=4096, N=1024
// MODE 3: expert L2  : Y  = He @ W2e                     M=CAP/e, K=4096, N=1024
template <int MODE>
__global__ __launch_bounds__(256) void gemm_kernel(const float* __restrict__ x,
                                                   const float* __restrict__ cond,
                                                   const float* __restrict__ W,
                                                   const float* __restrict__ mask,
                                                   float* __restrict__ out) {
    constexpr int BM = 128, BN = 128, BK = 32;
    constexpr int KDIM = (MODE <= 1) ? D_IN : D_FF;
    constexpr int NDIM = (MODE <= 1) ? D_FF : D_MODEL;
    constexpr int KT   = KDIM / BK;
    constexpr int ASTR = BK + 4;     // 36 floats: conflict-free A fragment reads
    constexpr int BSTR = BN + 8;     // 136 floats: conflict-free B fragment reads
    constexpr int ASZ  = BM * ASTR;  // 4608
    constexpr int BSZ  = BK * BSTR;  // 4352

    extern __shared__ float smem[];
    float* As = smem;             // 2 stages
    float* Bs = smem + 2 * ASZ;   // 2 stages

    const int tid = threadIdx.x;
    const int n0 = blockIdx.x * BN;
    const int m0 = blockIdx.y * BM;
    int e = 0;
    if (MODE == 1 || MODE == 3) {
        e = blockIdx.z;
        if (m0 >= g_cnt[e]) return;   // skip fully-empty tiles (uniform branch)
    }

    const float* Wp = W;
    if (MODE == 1) Wp = W + (size_t)e * D_IN * D_FF;
    if (MODE == 3) Wp = W + (size_t)e * D_FF * D_MODEL;

    // ---- loader geometry: A tile 128 rows x 32 cols, B tile 32 rows x 128 cols ----
    const int a_cc = tid & 7;    // 16B chunk within row (constant per thread)
    const int a_r0 = tid >> 3;   // rows a_r0 + 32*i
    const int b_cc = tid & 31;
    const int b_k0 = tid >> 5;

    int tok[4];
    const float* aptr[4];
    if (MODE == 0) {
#pragma unroll
        for (int i = 0; i < 4; i++) tok[i] = m0 + a_r0 + 32 * i;
    } else if (MODE == 1) {
#pragma unroll
        for (int i = 0; i < 4; i++) tok[i] = g_route[e * CAP + m0 + a_r0 + 32 * i];
    } else {
        const float* abase = (MODE == 2) ? g_Hs : (g_He + (size_t)e * CAP * D_FF);
#pragma unroll
        for (int i = 0; i < 4; i++)
            aptr[i] = abase + (size_t)(m0 + a_r0 + 32 * i) * D_FF + a_cc * 4;
    }

    auto load_tile = [&](int kt, int st) {
        const int k0 = kt * BK;
        float* as = As + st * ASZ;
        float* bs = Bs + st * BSZ;
        const int kc = k0 + a_cc * 4;
#pragma unroll
        for (int i = 0; i < 4; i++) {
            const float* src;
            if (MODE <= 1) {
                src = (kc < D_MODEL) ? (x + (size_t)tok[i] * D_MODEL + kc)
                                     : (cond + (size_t)tok[i] * D_COND + (kc - D_MODEL));
            } else {
                src = aptr[i] + k0;
            }
            cp16(as + (a_r0 + 32 * i) * ASTR + a_cc * 4, src);
        }
#pragma unroll
        for (int i = 0; i < 4; i++) {
            int kk = b_k0 + 8 * i;
            cp16(bs + kk * BSTR + b_cc * 4, Wp + (size_t)(k0 + kk) * NDIM + n0 + b_cc * 4);
        }
        asm volatile("cp.async.commit_group;" ::: "memory");
    };

    const int warp = tid >> 5, lane = tid & 31;
    const int wm = warp >> 2, wn = warp & 3;   // 2x4 warp grid; warp tile 64x32
    const int lr = lane >> 2, lc = lane & 3;

    float acc[4][4][4];
#pragma unroll
    for (int f = 0; f < 4; f++)
#pragma unroll
        for (int g = 0; g < 4; g++)
#pragma unroll
            for (int c = 0; c < 4; c++) acc[f][g][c] = 0.f;

    load_tile(0, 0);

    for (int kt = 0; kt < KT; kt++) {
        const int cur = kt & 1;
        if (kt + 1 < KT) {
            load_tile(kt + 1, cur ^ 1);
            asm volatile("cp.async.wait_group 1;" ::: "memory");
        } else {
            asm volatile("cp.async.wait_group 0;" ::: "memory");
        }
        __syncthreads();

        const float* as = As + cur * ASZ + (wm * 64 + lr) * ASTR + lc;
        const float* bs = Bs + cur * BSZ + wn * 32 + lr;
#pragma unroll
        for (int ks = 0; ks < 4; ks++) {
            const int kb = ks * 8;
            unsigned af[4][4], bf[4][2];
#pragma unroll
            for (int f = 0; f < 4; f++) {
                const float* p = as + f * 16 * ASTR + kb;
                af[f][0] = f2tf(p[0]);
                af[f][1] = f2tf(p[8 * ASTR]);
                af[f][2] = f2tf(p[4]);
                af[f][3] = f2tf(p[8 * ASTR + 4]);
            }
#pragma unroll
            for (int g = 0; g < 4; g++) {
                const float* p = bs + (kb + lc) * BSTR + g * 8;
                bf[g][0] = f2tf(p[0]);
                bf[g][1] = f2tf(p[4 * BSTR]);
            }
#pragma unroll
            for (int f = 0; f < 4; f++)
#pragma unroll
                for (int g = 0; g < 4; g++) {
                    asm volatile(
                        "mma.sync.aligned.m16n8k8.row.col.f32.tf32.tf32.f32 "
                        "{%0,%1,%2,%3}, {%4,%5,%6,%7}, {%8,%9}, {%0,%1,%2,%3};"
                        : "+f"(acc[f][g][0]), "+f"(acc[f][g][1]),
                          "+f"(acc[f][g][2]), "+f"(acc[f][g][3])
                        : "r"(af[f][0]), "r"(af[f][1]), "r"(af[f][2]), "r"(af[f][3]),
                          "r"(bf[g][0]), "r"(bf[g][1]));
                }
        }
        __syncthreads();
    }

    // ---- epilogue ----
#pragma unroll
    for (int f = 0; f < 4; f++) {
        const int row = m0 + wm * 64 + f * 16 + lr;   // +8 for c2/c3
#pragma unroll
        for (int g = 0; g < 4; g++) {
            const int col = n0 + wn * 32 + g * 8 + 2 * lc;
            if (MODE == 0 || MODE == 1) {
                float* dst = (MODE == 0) ? (g_Hs + (size_t)row * D_FF)
                                         : (g_He + ((size_t)e * CAP + row) * D_FF);
                float2 v0 = make_float2(gelu_f(acc[f][g][0]), gelu_f(acc[f][g][1]));
                float2 v1 = make_float2(gelu_f(acc[f][g][2]), gelu_f(acc[f][g][3]));
                *(float2*)(dst + col) = v0;
                *(float2*)(dst + (size_t)8 * D_FF + col) = v1;
            } else if (MODE == 2) {
                float mk0 = mask[row] * (1.f / 3.f);
                float mk1 = mask[row + 8] * (1.f / 3.f);
                float2 v0 = make_float2(acc[f][g][0] * mk0, acc[f][g][1] * mk0);
                float2 v1 = make_float2(acc[f][g][2] * mk1, acc[f][g][3] * mk1);
                *(float2*)(out + (size_t)row * D_MODEL + col) = v0;
                *(float2*)(out + (size_t)(row + 8) * D_MODEL + col) = v1;
            } else {
                float* dst = g_Y + ((size_t)e * CAP + row) * D_MODEL;
                *(float2*)(dst + col) = make_float2(acc[f][g][0], acc[f][g][1]);
                *(float2*)(dst + (size_t)8 * D_MODEL + col) = make_float2(acc[f][g][2], acc[f][g][3]);
            }
        }
    }
}

// ---------------- 4) combine: out += (2/3)*mask*(w0*Y[s0] + w1*Y[s1]) ----------------
__global__ __launch_bounds__(256) void combine_kernel(const float* __restrict__ mask,
                                                      float* __restrict__ out) {
    const int idx = blockIdx.x * 256 + threadIdx.x;   // one float4 per thread
    const int t = idx >> 8;
    const int c = (idx & 255) * 4;
    const int s0 = g_slot[2 * t], s1 = g_slot[2 * t + 1];
    const float w0 = g_weight[2 * t], w1 = g_weight[2 * t + 1];
    const float m = mask[t] * (2.f / 3.f);
    float ax = 0.f, ay = 0.f, az = 0.f, aw = 0.f;
    if (s0 >= 0) {
        float4 y = *(const float4*)(g_Y + (size_t)s0 * D_MODEL + c);
        ax += w0 * y.x; ay += w0 * y.y; az += w0 * y.z; aw += w0 * y.w;
    }
    if (s1 >= 0) {
        float4 y = *(const float4*)(g_Y + (size_t)s1 * D_MODEL + c);
        ax += w1 * y.x; ay += w1 * y.y; az += w1 * y.z; aw += w1 * y.w;
    }
    float4 o = *(float4*)(out + (size_t)t * D_MODEL + c);
    o.x += m * ax; o.y += m * ay; o.z += m * az; o.w += m * aw;
    *(float4*)(out + (size_t)t * D_MODEL + c) = o;
}

// ---------------- launch ----------------
extern "C" void kernel_launch(void* const* d_in, const int* in_sizes, int n_in,
                              void* d_out, int out_size) {
    const float* x    = (const float*)d_in[0];
    const float* cond = (const float*)d_in[1];
    const float* mask = (const float*)d_in[2];
    const float* Wr   = (const float*)d_in[3];
    const float* W1s  = (const float*)d_in[4];
    const float* W2s  = (const float*)d_in[5];
    const float* W1e  = (const float*)d_in[6];
    const float* W2e  = (const float*)d_in[7];
    float* out = (float*)d_out;

    const int smem = (2 * (128 * 36) + 2 * (32 * 136)) * (int)sizeof(float);  // 71680 B
    cudaFuncSetAttribute(gemm_kernel<0>, cudaFuncAttributeMaxDynamicSharedMemorySize, smem);
    cudaFuncSetAttribute(gemm_kernel<1>, cudaFuncAttributeMaxDynamicSharedMemorySize, smem);
    cudaFuncSetAttribute(gemm_kernel<2>, cudaFuncAttributeMaxDynamicSharedMemorySize, smem);
    cudaFuncSetAttribute(gemm_kernel<3>, cudaFuncAttributeMaxDynamicSharedMemorySize, smem);

    router_kernel<<<T_TOK / 8, 256>>>(x, Wr);
    binning_kernel<<<1, 512>>>();
    gemm_kernel<0><<<dim3(D_FF / 128, T_TOK / 128, 1),    256, smem>>>(x, cond, W1s, mask, out);
    gemm_kernel<1><<<dim3(D_FF / 128, CAP / 128, NEXP),   256, smem>>>(x, cond, W1e, mask, out);
    gemm_kernel<2><<<dim3(D_MODEL / 128, T_TOK / 128, 1), 256, smem>>>(x, cond, W2s, mask, out);
    gemm_kernel<3><<<dim3(D_MODEL / 128, CAP / 128, NEXP), 256, smem>>>(x, cond, W2e, mask, out);
    combine_kernel<<<T_TOK, 256>>>(mask, out);
}

// round 7
// speedup vs baseline: 1.0876x; 1.0876x over previous
#include <cuda_runtime.h>
#include <cuda_bf16.h>
#include <cstdint>

// ---------------- problem constants ----------------
#define T_TOK   8192
#define D_MODEL 1024
#define D_COND  256
#define D_IN    1280      // D_MODEL + D_COND
#define D_FF    4096
#define NEXP    8
#define TOPK    2
#define CAP     2560      // int(1.25 * 2 * 8192 / 8)
#define TKA     (T_TOK*TOPK)

// ---------------- device scratch (static, no runtime allocation) ----------------
__device__ int   g_expert[TKA];
__device__ float g_weight[TKA];
__device__ int   g_slot[TKA];
__device__ int   g_route[NEXP*CAP];
__device__ int   g_cnt[NEXP];
__device__ float g_xc[(size_t)T_TOK * D_IN];            // tf32-rounded [x|cond]
__device__ float g_Hs[(size_t)T_TOK * D_FF];            // shared hidden (tf32-rounded)
__device__ float g_He[(size_t)NEXP * CAP * D_FF];       // expert hidden (tf32-rounded)
__device__ float g_Y [(size_t)NEXP * CAP * D_MODEL];    // expert output (fp32)
__device__ float g_W1sR[(size_t)D_IN * D_FF];           // tf32-rounded weight copies
__device__ float g_W2sR[(size_t)D_FF * D_MODEL];
__device__ float g_W1eR[(size_t)NEXP * D_IN * D_FF];
__device__ float g_W2eR[(size_t)NEXP * D_FF * D_MODEL];

// ---------------- helpers ----------------
__device__ __forceinline__ unsigned f2tf(float f) {
    unsigned u;
    asm("cvt.rna.tf32.f32 %0, %1;" : "=r"(u) : "f"(f));
    return u;
}
__device__ __forceinline__ float rtf(float f) { return __uint_as_float(f2tf(f)); }
__device__ __forceinline__ void cp16(void* dst_smem, const void* src_gmem) {
    unsigned sa = (unsigned)__cvta_generic_to_shared(dst_smem);
    asm volatile("cp.async.cg.shared.global [%0], [%1], 16;" :: "r"(sa), "l"(src_gmem));
}
__device__ __forceinline__ float gelu_f(float v) {
    // jax.nn.gelu default (approximate=True, tanh form); accurate tanhf on purpose
    float u = 0.7978845608028654f * (v + 0.044715f * v * v * v);
    return 0.5f * v * (1.0f + tanhf(u));
}

// ---------------- 0a) pack + tf32-round [x|cond] ----------------
__global__ __launch_bounds__(256) void pack_round_kernel(const float* __restrict__ x,
                                                         const float* __restrict__ cond) {
    int i = blockIdx.x * 256 + threadIdx.x;        // float4 index; rows have 320 float4
    int t = i / 320, c4 = i % 320;
    float4 v;
    if (c4 < 256) v = ((const float4*)x)[(size_t)t * 256 + c4];
    else          v = ((const float4*)cond)[(size_t)t * 64 + (c4 - 256)];
    v.x = rtf(v.x); v.y = rtf(v.y); v.z = rtf(v.z); v.w = rtf(v.w);
    ((float4*)g_xc)[(size_t)t * 320 + c4] = v;
}

// ---------------- 0b) tf32-round copy (same layout) ----------------
__global__ __launch_bounds__(256) void round_copy_kernel(const float* __restrict__ src,
                                                         float* __restrict__ dst) {
    size_t i = (size_t)blockIdx.x * 256 + threadIdx.x;   // float4 index
    float4 v = ((const float4*)src)[i];
    v.x = rtf(v.x); v.y = rtf(v.y); v.z = rtf(v.z); v.w = rtf(v.w);
    ((float4*)dst)[i] = v;
}

// ---------------- 1) router ----------------
__global__ __launch_bounds__(256) void router_kernel(const float* __restrict__ x,
                                                     const float* __restrict__ Wr) {
    __shared__ float sWr[D_MODEL * NEXP];
    const int tid = threadIdx.x;
    for (int i = tid; i < D_MODEL * NEXP; i += 256) sWr[i] = Wr[i];
    __syncthreads();

    const int warp = tid >> 5, lane = tid & 31;
    const int t = blockIdx.x * 8 + warp;
    const float* xr = x + (size_t)t * D_MODEL;

    float acc[NEXP];
#pragma unroll
    for (int e = 0; e < NEXP; e++) acc[e] = 0.f;
    for (int j = lane; j < D_MODEL; j += 32) {
        float xv = xr[j];
        const float* wrow = sWr + j * NEXP;
#pragma unroll
        for (int e = 0; e < NEXP; e++) acc[e] += xv * wrow[e];
    }
#pragma unroll
    for (int e = 0; e < NEXP; e++)
#pragma unroll
        for (int o = 16; o > 0; o >>= 1) acc[e] += __shfl_xor_sync(0xffffffffu, acc[e], o);

    if (lane == 0) {
        float mx = acc[0];
#pragma unroll
        for (int e = 1; e < NEXP; e++) mx = fmaxf(mx, acc[e]);
        float p[NEXP];
#pragma unroll
        for (int e = 0; e < NEXP; e++) p[e] = expf(acc[e] - mx);
        int i1 = 0; float v1 = p[0];
#pragma unroll
        for (int e = 1; e < NEXP; e++) if (p[e] > v1) { v1 = p[e]; i1 = e; }
        int i2 = -1; float v2 = -1.f;
#pragma unroll
        for (int e = 0; e < NEXP; e++) if (e != i1 && p[e] > v2) { v2 = p[e]; i2 = e; }
        float inv = 1.f / (v1 + v2);   // softmax denom cancels in normalization
        g_expert[2 * t]     = i1;  g_weight[2 * t]     = v1 * inv;
        g_expert[2 * t + 1] = i2;  g_weight[2 * t + 1] = v2 * inv;
    }
}

// ---------------- 2) binning: deterministic stable per-expert ranks ----------------
__global__ __launch_bounds__(512) void binning_kernel() {
    __shared__ int scnt[512 * NEXP];
    const int tid = threadIdx.x;
    for (int i = tid; i < NEXP * CAP; i += 512) g_route[i] = 0;

    const int base = tid * (TKA / 512);
    int loc[NEXP];
#pragma unroll
    for (int e = 0; e < NEXP; e++) loc[e] = 0;
    for (int i = 0; i < TKA / 512; i++) loc[g_expert[base + i]]++;
#pragma unroll
    for (int e = 0; e < NEXP; e++) scnt[tid * NEXP + e] = loc[e];
    __syncthreads();

    if (tid < NEXP) {
        int run = 0;
        for (int i = 0; i < 512; i++) {
            int v = scnt[i * NEXP + tid];
            scnt[i * NEXP + tid] = run;
            run += v;
        }
        g_cnt[tid] = min(run, CAP);
    }
    __syncthreads();

    int offs[NEXP];
#pragma unroll
    for (int e = 0; e < NEXP; e++) offs[e] = scnt[tid * NEXP + e];
    for (int i = 0; i < TKA / 512; i++) {
        int a = base + i;
        int e = g_expert[a];
        int pos = offs[e]++;
        if (pos < CAP) {
            int slot = e * CAP + pos;
            g_route[slot] = a >> 1;
            g_slot[a] = slot;
        } else {
            g_slot[a] = -1;
        }
    }
}

// ---------------- 3) tiled tf32 GEMM (mma.sync m16n8k8, pre-rounded operands) ----------------
// All sources are already tf32-rounded bit patterns -> mainloop is LDS + HMMA only.
// MODE 0: g_Hs = rtf(gelu(g_xc @ W1s))           M=8192, K=1280, N=4096
// MODE 1: g_He = rtf(gelu(gather(g_xc) @ W1e))   M<=CAP, K=1280, N=4096
// MODE 2: out  = mask/3 * (g_Hs @ W2s)           M=8192, K=4096, N=1024
// MODE 3: g_Y  = g_He @ W2e                      M<=CAP, K=4096, N=1024
template <int MODE>
__global__ __launch_bounds__(256, 2) void gemm_kernel(const float* __restrict__ mask,
                                                      float* __restrict__ out) {
    constexpr int BM = 128, BN = 128, BK = 32;
    constexpr int KDIM = (MODE <= 1) ? D_IN : D_FF;
    constexpr int NDIM = (MODE <= 1) ? D_FF : D_MODEL;
    constexpr int KT   = KDIM / BK;
    constexpr int ASTR = BK + 4;     // 36 floats
    constexpr int BSTR = BN + 8;     // 136 floats
    constexpr int ASZ  = BM * ASTR;
    constexpr int BSZ  = BK * BSTR;

    extern __shared__ float smem[];
    float* As = smem;
    float* Bs = smem + 2 * ASZ;

    const int tid = threadIdx.x;
    const int n0 = blockIdx.x * BN;
    const int m0 = blockIdx.y * BM;
    int e = 0;
    if (MODE == 1 || MODE == 3) {
        e = blockIdx.z;
        if (m0 >= g_cnt[e]) return;   // uniform skip of empty tiles
    }

    const float* Ab;
    const float* Wp;
    if (MODE == 0)      { Ab = g_xc;                          Wp = g_W1sR; }
    else if (MODE == 1) { Ab = g_xc;                          Wp = g_W1eR + (size_t)e * D_IN * D_FF; }
    else if (MODE == 2) { Ab = g_Hs;                          Wp = g_W2sR; }
    else                { Ab = g_He + (size_t)e * CAP * D_FF; Wp = g_W2eR + (size_t)e * D_FF * D_MODEL; }

    // ---- loader geometry: A tile 128x32, B tile 32x128 ----
    const int a_cc = tid & 7;
    const int a_r0 = tid >> 3;
    const int b_cc = tid & 31;
    const int b_k0 = tid >> 5;

    const float* aptr[4];
#pragma unroll
    for (int i = 0; i < 4; i++) {
        int r = m0 + a_r0 + 32 * i;
        int row = (MODE == 1) ? g_route[e * CAP + r] : r;
        aptr[i] = Ab + (size_t)row * KDIM + a_cc * 4;
    }

    auto load_tile = [&](int kt, int st) {
        const int k0 = kt * BK;
        float* as = As + st * ASZ;
        float* bs = Bs + st * BSZ;
#pragma unroll
        for (int i = 0; i < 4; i++)
            cp16(as + (a_r0 + 32 * i) * ASTR + a_cc * 4, aptr[i] + k0);
#pragma unroll
        for (int i = 0; i < 4; i++) {
            int kk = b_k0 + 8 * i;
            cp16(bs + kk * BSTR + b_cc * 4, Wp + (size_t)(k0 + kk) * NDIM + n0 + b_cc * 4);
        }
        asm volatile("cp.async.commit_group;" ::: "memory");
    };

    const int warp = tid >> 5, lane = tid & 31;
    const int wm = warp >> 2, wn = warp & 3;   // 2x4 warp grid; warp tile 64x32
    const int lr = lane >> 2, lc = lane & 3;

    float acc[4][4][4];
#pragma unroll
    for (int f = 0; f < 4; f++)
#pragma unroll
        for (int g = 0; g < 4; g++)
#pragma unroll
            for (int c = 0; c < 4; c++) acc[f][g][c] = 0.f;

    load_tile(0, 0);

    for (int kt = 0; kt < KT; kt++) {
        const int cur = kt & 1;
        if (kt + 1 < KT) {
            load_tile(kt + 1, cur ^ 1);
            asm volatile("cp.async.wait_group 1;" ::: "memory");
        } else {
            asm volatile("cp.async.wait_group 0;" ::: "memory");
        }
        __syncthreads();

        const float* as = As + cur * ASZ + (wm * 64 + lr) * ASTR + lc;
        const float* bs = Bs + cur * BSZ + wn * 32 + lr;
#pragma unroll
        for (int ks = 0; ks < 4; ks++) {
            const int kb = ks * 8;
            unsigned af[4][4], bf[4][2];
#pragma unroll
            for (int f = 0; f < 4; f++) {
                const float* p = as + f * 16 * ASTR + kb;
                af[f][0] = __float_as_uint(p[0]);            // pre-rounded: no cvt
                af[f][1] = __float_as_uint(p[8 * ASTR]);
                af[f][2] = __float_as_uint(p[4]);
                af[f][3] = __float_as_uint(p[8 * ASTR + 4]);
            }
#pragma unroll
            for (int g = 0; g < 4; g++) {
                const float* p = bs + (kb + lc) * BSTR + g * 8;
                bf[g][0] = __float_as_uint(p[0]);
                bf[g][1] = __float_as_uint(p[4 * BSTR]);
            }
#pragma unroll
            for (int f = 0; f < 4; f++)
#pragma unroll
                for (int g = 0; g < 4; g++) {
                    asm volatile(
                        "mma.sync.aligned.m16n8k8.row.col.f32.tf32.tf32.f32 "
                        "{%0,%1,%2,%3}, {%4,%5,%6,%7}, {%8,%9}, {%0,%1,%2,%3};"
                        : "+f"(acc[f][g][0]), "+f"(acc[f][g][1]),
                          "+f"(acc[f][g][2]), "+f"(acc[f][g][3])
                        : "r"(af[f][0]), "r"(af[f][1]), "r"(af[f][2]), "r"(af[f][3]),
                          "r"(bf[g][0]), "r"(bf[g][1]));
                }
        }
        __syncthreads();
    }

    // ---- epilogue ----
#pragma unroll
    for (int f = 0; f < 4; f++) {
        const int row = m0 + wm * 64 + f * 16 + lr;   // +8 for c2/c3
#pragma unroll
        for (int g = 0; g < 4; g++) {
            const int col = n0 + wn * 32 + g * 8 + 2 * lc;
            if (MODE == 0 || MODE == 1) {
                float* dst = (MODE == 0) ? (g_Hs + (size_t)row * D_FF)
                                         : (g_He + ((size_t)e * CAP + row) * D_FF);
                float2 v0 = make_float2(rtf(gelu_f(acc[f][g][0])), rtf(gelu_f(acc[f][g][1])));
                float2 v1 = make_float2(rtf(gelu_f(acc[f][g][2])), rtf(gelu_f(acc[f][g][3])));
                *(float2*)(dst + col) = v0;
                *(float2*)(dst + (size_t)8 * D_FF + col) = v1;
            } else if (MODE == 2) {
                float mk0 = mask[row] * (1.f / 3.f);
                float mk1 = mask[row + 8] * (1.f / 3.f);
                float2 v0 = make_float2(acc[f][g][0] * mk0, acc[f][g][1] * mk0);
                float2 v1 = make_float2(acc[f][g][2] * mk1, acc[f][g][3] * mk1);
                *(float2*)(out + (size_t)row * D_MODEL + col) = v0;
                *(float2*)(out + (size_t)(row + 8) * D_MODEL + col) = v1;
            } else {
                float* dst = g_Y + ((size_t)e * CAP + row) * D_MODEL;
                *(float2*)(dst + col) = make_float2(acc[f][g][0], acc[f][g][1]);
                *(float2*)(dst + (size_t)8 * D_MODEL + col) = make_float2(acc[f][g][2], acc[f][g][3]);
            }
        }
    }
}

// ---------------- 4) combine: out += (2/3)*mask*(w0*Y[s0] + w1*Y[s1]) ----------------
__global__ __launch_bounds__(256) void combine_kernel(const float* __restrict__ mask,
                                                      float* __restrict__ out) {
    const int idx = blockIdx.x * 256 + threadIdx.x;
    const int t = idx >> 8;
    const int c = (idx & 255) * 4;
    const int s0 = g_slot[2 * t], s1 = g_slot[2 * t + 1];
    const float w0 = g_weight[2 * t], w1 = g_weight[2 * t + 1];
    const float m = mask[t] * (2.f / 3.f);
    float ax = 0.f, ay = 0.f, az = 0.f, aw = 0.f;
    if (s0 >= 0) {
        float4 y = *(const float4*)(g_Y + (size_t)s0 * D_MODEL + c);
        ax += w0 * y.x; ay += w0 * y.y; az += w0 * y.z; aw += w0 * y.w;
    }
    if (s1 >= 0) {
        float4 y = *(const float4*)(g_Y + (size_t)s1 * D_MODEL + c);
        ax += w1 * y.x; ay += w1 * y.y; az += w1 * y.z; aw += w1 * y.w;
    }
    float4 o = *(float4*)(out + (size_t)t * D_MODEL + c);
    o.x += m * ax; o.y += m * ay; o.z += m * az; o.w += m * aw;
    *(float4*)(out + (size_t)t * D_MODEL + c) = o;
}

// ---------------- launch ----------------
extern "C" void kernel_launch(void* const* d_in, const int* in_sizes, int n_in,
                              void* d_out, int out_size) {
    const float* x    = (const float*)d_in[0];
    const float* cond = (const float*)d_in[1];
    const float* mask = (const float*)d_in[2];
    const float* Wr   = (const float*)d_in[3];
    const float* W1s  = (const float*)d_in[4];
    const float* W2s  = (const float*)d_in[5];
    const float* W1e  = (const float*)d_in[6];
    const float* W2e  = (const float*)d_in[7];
    float* out = (float*)d_out;

    const int smem = (2 * (128 * 36) + 2 * (32 * 136)) * (int)sizeof(float);  // 71680 B
    cudaFuncSetAttribute(gemm_kernel<0>, cudaFuncAttributeMaxDynamicSharedMemorySize, smem);
    cudaFuncSetAttribute(gemm_kernel<1>, cudaFuncAttributeMaxDynamicSharedMemorySize, smem);
    cudaFuncSetAttribute(gemm_kernel<2>, cudaFuncAttributeMaxDynamicSharedMemorySize, smem);
    cudaFuncSetAttribute(gemm_kernel<3>, cudaFuncAttributeMaxDynamicSharedMemorySize, smem);

    float* w1s; cudaGetSymbolAddress((void**)&w1s, g_W1sR);
    float* w2s; cudaGetSymbolAddress((void**)&w2s, g_W2sR);
    float* w1e; cudaGetSymbolAddress((void**)&w1e, g_W1eR);
    float* w2e; cudaGetSymbolAddress((void**)&w2e, g_W2eR);

    // pre-round all GEMM operands to tf32 (rna), once
    pack_round_kernel<<<T_TOK * 320 / 256, 256>>>(x, cond);
    round_copy_kernel<<<(D_IN * D_FF) / 1024, 256>>>(W1s, w1s);
    round_copy_kernel<<<(D_FF * D_MODEL) / 1024, 256>>>(W2s, w2s);
    round_copy_kernel<<<(NEXP * D_IN * D_FF) / 1024, 256>>>(W1e, w1e);
    round_copy_kernel<<<(NEXP * D_FF * D_MODEL) / 1024, 256>>>(W2e, w2e);

    router_kernel<<<T_TOK / 8, 256>>>(x, Wr);
    binning_kernel<<<1, 512>>>();

    gemm_kernel<0><<<dim3(D_FF / 128, T_TOK / 128, 1),     256, smem>>>(mask, out);
    gemm_kernel<1><<<dim3(D_FF / 128, CAP / 128, NEXP),    256, smem>>>(mask, out);
    gemm_kernel<2><<<dim3(D_MODEL / 128, T_TOK / 128, 1),  256, smem>>>(mask, out);
    gemm_kernel<3><<<dim3(D_MODEL / 128, CAP / 128, NEXP), 256, smem>>>(mask, out);

    combine_kernel<<<T_TOK, 256>>>(mask, out);
}

// round 8
// speedup vs baseline: 1.1267x; 1.0359x over previous
#include <cuda_runtime.h>
#include <cuda_bf16.h>
#include <cstdint>

// ---------------- problem constants ----------------
#define T_TOK   8192
#define D_MODEL 1024
#define D_COND  256
#define D_IN    1280      // D_MODEL + D_COND
#define D_FF    4096
#define NEXP    8
#define TOPK    2
#define CAP     2560      // int(1.25 * 2 * 8192 / 8)
#define TKA     (T_TOK*TOPK)

// ---------------- device scratch (static, no runtime allocation) ----------------
__device__ int   g_expert[TKA];
__device__ float g_weight[TKA];
__device__ int   g_slot[TKA];
__device__ int   g_route[NEXP*CAP];
__device__ int   g_cnt[NEXP];
__device__ float g_xc[(size_t)T_TOK * D_IN];            // tf32-rounded [x|cond]
__device__ float g_Hs[(size_t)T_TOK * D_FF];            // shared hidden (tf32-rounded)
__device__ float g_He[(size_t)NEXP * CAP * D_FF];       // expert hidden (tf32-rounded)
__device__ float g_Y [(size_t)NEXP * CAP * D_MODEL];    // expert output (fp32)
__device__ float g_W1sR[(size_t)D_IN * D_FF];           // tf32-rounded weight copies
__device__ float g_W2sR[(size_t)D_FF * D_MODEL];
__device__ float g_W1eR[(size_t)NEXP * D_IN * D_FF];
__device__ float g_W2eR[(size_t)NEXP * D_FF * D_MODEL];

// ---------------- helpers ----------------
__device__ __forceinline__ unsigned f2tf(float f) {
    unsigned u;
    asm("cvt.rna.tf32.f32 %0, %1;" : "=r"(u) : "f"(f));
    return u;
}
__device__ __forceinline__ float rtf(float f) { return __uint_as_float(f2tf(f)); }
__device__ __forceinline__ void cp16(void* dst_smem, const void* src_gmem) {
    unsigned sa = (unsigned)__cvta_generic_to_shared(dst_smem);
    asm volatile("cp.async.cg.shared.global [%0], [%1], 16;" :: "r"(sa), "l"(src_gmem));
}
__device__ __forceinline__ float gelu_f(float v) {
    // jax.nn.gelu (tanh form), HW tanh.approx (max rel err ~2^-11 on t)
    float u = 0.7978845608028654f * (v + 0.044715f * v * v * v);
    float t;
    asm("tanh.approx.f32 %0, %1;" : "=f"(t) : "f"(u));
    return 0.5f * v * (1.0f + t);
}

// ---------------- 0a) pack + tf32-round [x|cond] ----------------
__global__ __launch_bounds__(256) void pack_round_kernel(const float* __restrict__ x,
                                                         const float* __restrict__ cond) {
    int i = blockIdx.x * 256 + threadIdx.x;        // float4 index; rows have 320 float4
    int t = i / 320, c4 = i % 320;
    float4 v;
    if (c4 < 256) v = ((const float4*)x)[(size_t)t * 256 + c4];
    else          v = ((const float4*)cond)[(size_t)t * 64 + (c4 - 256)];
    v.x = rtf(v.x); v.y = rtf(v.y); v.z = rtf(v.z); v.w = rtf(v.w);
    ((float4*)g_xc)[(size_t)t * 320 + c4] = v;
}

// ---------------- 0b) tf32-round copy (same layout) ----------------
__global__ __launch_bounds__(256) void round_copy_kernel(const float* __restrict__ src,
                                                         float* __restrict__ dst) {
    size_t i = (size_t)blockIdx.x * 256 + threadIdx.x;   // float4 index
    float4 v = ((const float4*)src)[i];
    v.x = rtf(v.x); v.y = rtf(v.y); v.z = rtf(v.z); v.w = rtf(v.w);
    ((float4*)dst)[i] = v;
}

// ---------------- 1) router ----------------
__global__ __launch_bounds__(256) void router_kernel(const float* __restrict__ x,
                                                     const float* __restrict__ Wr) {
    __shared__ float sWr[D_MODEL * NEXP];
    const int tid = threadIdx.x;
    for (int i = tid; i < D_MODEL * NEXP; i += 256) sWr[i] = Wr[i];
    __syncthreads();

    const int warp = tid >> 5, lane = tid & 31;
    const int t = blockIdx.x * 8 + warp;
    const float* xr = x + (size_t)t * D_MODEL;

    float acc[NEXP];
#pragma unroll
    for (int e = 0; e < NEXP; e++) acc[e] = 0.f;
    for (int j = lane; j < D_MODEL; j += 32) {
        float xv = xr[j];
        const float* wrow = sWr + j * NEXP;
#pragma unroll
        for (int e = 0; e < NEXP; e++) acc[e] += xv * wrow[e];
    }
#pragma unroll
    for (int e = 0; e < NEXP; e++)
#pragma unroll
        for (int o = 16; o > 0; o >>= 1) acc[e] += __shfl_xor_sync(0xffffffffu, acc[e], o);

    if (lane == 0) {
        float mx = acc[0];
#pragma unroll
        for (int e = 1; e < NEXP; e++) mx = fmaxf(mx, acc[e]);
        float p[NEXP];
#pragma unroll
        for (int e = 0; e < NEXP; e++) p[e] = expf(acc[e] - mx);
        int i1 = 0; float v1 = p[0];
#pragma unroll
        for (int e = 1; e < NEXP; e++) if (p[e] > v1) { v1 = p[e]; i1 = e; }
        int i2 = -1; float v2 = -1.f;
#pragma unroll
        for (int e = 0; e < NEXP; e++) if (e != i1 && p[e] > v2) { v2 = p[e]; i2 = e; }
        float inv = 1.f / (v1 + v2);   // softmax denom cancels in normalization
        g_expert[2 * t]     = i1;  g_weight[2 * t]     = v1 * inv;
        g_expert[2 * t + 1] = i2;  g_weight[2 * t + 1] = v2 * inv;
    }
}

// ---------------- 2) binning: deterministic stable per-expert ranks ----------------
__global__ __launch_bounds__(512) void binning_kernel() {
    __shared__ int scnt[512 * NEXP];
    const int tid = threadIdx.x;
    for (int i = tid; i < NEXP * CAP; i += 512) g_route[i] = 0;

    const int base = tid * (TKA / 512);
    int loc[NEXP];
#pragma unroll
    for (int e = 0; e < NEXP; e++) loc[e] = 0;
    for (int i = 0; i < TKA / 512; i++) loc[g_expert[base + i]]++;
#pragma unroll
    for (int e = 0; e < NEXP; e++) scnt[tid * NEXP + e] = loc[e];
    __syncthreads();

    if (tid < NEXP) {
        int run = 0;
        for (int i = 0; i < 512; i++) {
            int v = scnt[i * NEXP + tid];
            scnt[i * NEXP + tid] = run;
            run += v;
        }
        g_cnt[tid] = min(run, CAP);
    }
    __syncthreads();

    int offs[NEXP];
#pragma unroll
    for (int e = 0; e < NEXP; e++) offs[e] = scnt[tid * NEXP + e];
    for (int i = 0; i < TKA / 512; i++) {
        int a = base + i;
        int e = g_expert[a];
        int pos = offs[e]++;
        if (pos < CAP) {
            int slot = e * CAP + pos;
            g_route[slot] = a >> 1;
            g_slot[a] = slot;
        } else {
            g_slot[a] = -1;
        }
    }
}

// ---------------- 3) tiled tf32 GEMM: 128x128 CTA tile, 4 warps, 64x64 warp tile ----------------
// All operands pre-rounded to tf32 -> mainloop is pure LDS + HMMA.
// MODE 0: g_Hs = rtf(gelu(g_xc @ W1s))           M=8192, K=1280, N=4096
// MODE 1: g_He = rtf(gelu(gather(g_xc) @ W1e))   M<=CAP, K=1280, N=4096
// MODE 2: out  = mask/3 * (g_Hs @ W2s)           M=8192, K=4096, N=1024
// MODE 3: g_Y  = g_He @ W2e                      M<=CAP, K=4096, N=1024
template <int MODE>
__global__ __launch_bounds__(128, 2) void gemm_kernel(const float* __restrict__ mask,
                                                      float* __restrict__ out) {
    constexpr int BM = 128, BN = 128, BK = 32;
    constexpr int KDIM = (MODE <= 1) ? D_IN : D_FF;
    constexpr int NDIM = (MODE <= 1) ? D_FF : D_MODEL;
    constexpr int KT   = KDIM / BK;
    constexpr int ASTR = BK + 4;     // 36 floats
    constexpr int BSTR = BN + 8;     // 136 floats
    constexpr int ASZ  = BM * ASTR;  // 4608
    constexpr int BSZ  = BK * BSTR;  // 4352

    extern __shared__ float smem[];
    float* As = smem;
    float* Bs = smem + 2 * ASZ;

    const int tid = threadIdx.x;
    const int n0 = blockIdx.x * BN;
    const int m0 = blockIdx.y * BM;
    int e = 0;
    if (MODE == 1 || MODE == 3) {
        e = blockIdx.z;
        if (m0 >= g_cnt[e]) return;   // uniform skip of empty tiles
    }

    const float* Ab;
    const float* Wp;
    if (MODE == 0)      { Ab = g_xc;                          Wp = g_W1sR; }
    else if (MODE == 1) { Ab = g_xc;                          Wp = g_W1eR + (size_t)e * D_IN * D_FF; }
    else if (MODE == 2) { Ab = g_Hs;                          Wp = g_W2sR; }
    else                { Ab = g_He + (size_t)e * CAP * D_FF; Wp = g_W2eR + (size_t)e * D_FF * D_MODEL; }

    // ---- loader geometry (128 threads): A tile 128x32 (8 cp16/thr), B tile 32x128 (8 cp16/thr) ----
    const int a_cc = tid & 7;    // 16B chunk in row
    const int a_r0 = tid >> 3;   // rows a_r0 + 16*i
    const int b_cc = tid & 31;
    const int b_k0 = tid >> 5;   // k rows b_k0 + 4*i

    const float* aptr[8];
#pragma unroll
    for (int i = 0; i < 8; i++) {
        int r = m0 + a_r0 + 16 * i;
        int row = (MODE == 1) ? g_route[e * CAP + r] : r;
        aptr[i] = Ab + (size_t)row * KDIM + a_cc * 4;
    }

    auto load_tile = [&](int kt, int st) {
        const int k0 = kt * BK;
        float* as = As + st * ASZ;
        float* bs = Bs + st * BSZ;
#pragma unroll
        for (int i = 0; i < 8; i++)
            cp16(as + (a_r0 + 16 * i) * ASTR + a_cc * 4, aptr[i] + k0);
#pragma unroll
        for (int i = 0; i < 8; i++) {
            int kk = b_k0 + 4 * i;
            cp16(bs + kk * BSTR + b_cc * 4, Wp + (size_t)(k0 + kk) * NDIM + n0 + b_cc * 4);
        }
        asm volatile("cp.async.commit_group;" ::: "memory");
    };

    const int warp = tid >> 5, lane = tid & 31;
    const int wm = warp >> 1, wn = warp & 1;   // 2x2 warp grid; warp tile 64x64
    const int lr = lane >> 2, lc = lane & 3;

    float acc[4][8][4];
#pragma unroll
    for (int f = 0; f < 4; f++)
#pragma unroll
        for (int g = 0; g < 8; g++)
#pragma unroll
            for (int c = 0; c < 4; c++) acc[f][g][c] = 0.f;

    load_tile(0, 0);

    for (int kt = 0; kt < KT; kt++) {
        const int cur = kt & 1;
        if (kt + 1 < KT) {
            load_tile(kt + 1, cur ^ 1);
            asm volatile("cp.async.wait_group 1;" ::: "memory");
        } else {
            asm volatile("cp.async.wait_group 0;" ::: "memory");
        }
        __syncthreads();

        const float* as = As + cur * ASZ + (wm * 64 + lr) * ASTR + lc;
        const float* bs = Bs + cur * BSZ + wn * 64 + lr;
#pragma unroll
        for (int ks = 0; ks < 4; ks++) {
            const int kb = ks * 8;
            unsigned af[4][4], bf[8][2];
#pragma unroll
            for (int f = 0; f < 4; f++) {
                const float* p = as + f * 16 * ASTR + kb;
                af[f][0] = __float_as_uint(p[0]);
                af[f][1] = __float_as_uint(p[8 * ASTR]);
                af[f][2] = __float_as_uint(p[4]);
                af[f][3] = __float_as_uint(p[8 * ASTR + 4]);
            }
#pragma unroll
            for (int g = 0; g < 8; g++) {
                const float* p = bs + (kb + lc) * BSTR + g * 8;
                bf[g][0] = __float_as_uint(p[0]);
                bf[g][1] = __float_as_uint(p[4 * BSTR]);
            }
#pragma unroll
            for (int f = 0; f < 4; f++)
#pragma unroll
                for (int g = 0; g < 8; g++) {
                    asm volatile(
                        "mma.sync.aligned.m16n8k8.row.col.f32.tf32.tf32.f32 "
                        "{%0,%1,%2,%3}, {%4,%5,%6,%7}, {%8,%9}, {%0,%1,%2,%3};"
                        : "+f"(acc[f][g][0]), "+f"(acc[f][g][1]),
                          "+f"(acc[f][g][2]), "+f"(acc[f][g][3])
                        : "r"(af[f][0]), "r"(af[f][1]), "r"(af[f][2]), "r"(af[f][3]),
                          "r"(bf[g][0]), "r"(bf[g][1]));
                }
        }
        __syncthreads();
    }

    // ---- epilogue ----
#pragma unroll
    for (int f = 0; f < 4; f++) {
        const int row = m0 + wm * 64 + f * 16 + lr;   // +8 for c2/c3
#pragma unroll
        for (int g = 0; g < 8; g++) {
            const int col = n0 + wn * 64 + g * 8 + 2 * lc;
            if (MODE == 0 || MODE == 1) {
                float* dst = (MODE == 0) ? (g_Hs + (size_t)row * D_FF)
                                         : (g_He + ((size_t)e * CAP + row) * D_FF);
                float2 v0 = make_float2(rtf(gelu_f(acc[f][g][0])), rtf(gelu_f(acc[f][g][1])));
                float2 v1 = make_float2(rtf(gelu_f(acc[f][g][2])), rtf(gelu_f(acc[f][g][3])));
                *(float2*)(dst + col) = v0;
                *(float2*)(dst + (size_t)8 * D_FF + col) = v1;
            } else if (MODE == 2) {
                float mk0 = mask[row] * (1.f / 3.f);
                float mk1 = mask[row + 8] * (1.f / 3.f);
                float2 v0 = make_float2(acc[f][g][0] * mk0, acc[f][g][1] * mk0);
                float2 v1 = make_float2(acc[f][g][2] * mk1, acc[f][g][3] * mk1);
                *(float2*)(out + (size_t)row * D_MODEL + col) = v0;
                *(float2*)(out + (size_t)(row + 8) * D_MODEL + col) = v1;
            } else {
                float* dst = g_Y + ((size_t)e * CAP + row) * D_MODEL;
                *(float2*)(dst + col) = make_float2(acc[f][g][0], acc[f][g][1]);
                *(float2*)(dst + (size_t)8 * D_MODEL + col) = make_float2(acc[f][g][2], acc[f][g][3]);
            }
        }
    }
}

// ---------------- 4) combine: out += (2/3)*mask*(w0*Y[s0] + w1*Y[s1]) ----------------
__global__ __launch_bounds__(256) void combine_kernel(const float* __restrict__ mask,
                                                      float* __restrict__ out) {
    const int idx = blockIdx.x * 256 + threadIdx.x;
    const int t = idx >> 8;
    const int c = (idx & 255) * 4;
    const int s0 = g_slot[2 * t], s1 = g_slot[2 * t + 1];
    const float w0 = g_weight[2 * t], w1 = g_weight[2 * t + 1];
    const float m = mask[t] * (2.f / 3.f);
    float ax = 0.f, ay = 0.f, az = 0.f, aw = 0.f;
    if (s0 >= 0) {
        float4 y = *(const float4*)(g_Y + (size_t)s0 * D_MODEL + c);
        ax += w0 * y.x; ay += w0 * y.y; az += w0 * y.z; aw += w0 * y.w;
    }
    if (s1 >= 0) {
        float4 y = *(const float4*)(g_Y + (size_t)s1 * D_MODEL + c);
        ax += w1 * y.x; ay += w1 * y.y; az += w1 * y.z; aw += w1 * y.w;
    }
    float4 o = *(float4*)(out + (size_t)t * D_MODEL + c);
    o.x += m * ax; o.y += m * ay; o.z += m * az; o.w += m * aw;
    *(float4*)(out + (size_t)t * D_MODEL + c) = o;
}

// ---------------- launch ----------------
extern "C" void kernel_launch(void* const* d_in, const int* in_sizes, int n_in,
                              void* d_out, int out_size) {
    const float* x    = (const float*)d_in[0];
    const float* cond = (const float*)d_in[1];
    const float* mask = (const float*)d_in[2];
    const float* Wr   = (const float*)d_in[3];
    const float* W1s  = (const float*)d_in[4];
    const float* W2s  = (const float*)d_in[5];
    const float* W1e  = (const float*)d_in[6];
    const float* W2e  = (const float*)d_in[7];
    float* out = (float*)d_out;

    const int smem = (2 * (128 * 36) + 2 * (32 * 136)) * (int)sizeof(float);  // 71680 B
    cudaFuncSetAttribute(gemm_kernel<0>, cudaFuncAttributeMaxDynamicSharedMemorySize, smem);
    cudaFuncSetAttribute(gemm_kernel<1>, cudaFuncAttributeMaxDynamicSharedMemorySize, smem);
    cudaFuncSetAttribute(gemm_kernel<2>, cudaFuncAttributeMaxDynamicSharedMemorySize, smem);
    cudaFuncSetAttribute(gemm_kernel<3>, cudaFuncAttributeMaxDynamicSharedMemorySize, smem);

    float* w1s; cudaGetSymbolAddress((void**)&w1s, g_W1sR);
    float* w2s; cudaGetSymbolAddress((void**)&w2s, g_W2sR);
    float* w1e; cudaGetSymbolAddress((void**)&w1e, g_W1eR);
    float* w2e; cudaGetSymbolAddress((void**)&w2e, g_W2eR);

    // pre-round all GEMM operands to tf32 (rna), once
    pack_round_kernel<<<T_TOK * 320 / 256, 256>>>(x, cond);
    round_copy_kernel<<<(D_IN * D_FF) / 1024, 256>>>(W1s, w1s);
    round_copy_kernel<<<(D_FF * D_MODEL) / 1024, 256>>>(W2s, w2s);
    round_copy_kernel<<<(NEXP * D_IN * D_FF) / 1024, 256>>>(W1e, w1e);
    round_copy_kernel<<<(NEXP * D_FF * D_MODEL) / 1024, 256>>>(W2e, w2e);

    router_kernel<<<T_TOK / 8, 256>>>(x, Wr);
    binning_kernel<<<1, 512>>>();

    gemm_kernel<0><<<dim3(D_FF / 128, T_TOK / 128, 1),     128, smem>>>(mask, out);
    gemm_kernel<1><<<dim3(D_FF / 128, CAP / 128, NEXP),    128, smem>>>(mask, out);
    gemm_kernel<2><<<dim3(D_MODEL / 128, T_TOK / 128, 1),  128, smem>>>(mask, out);
    gemm_kernel<3><<<dim3(D_MODEL / 128, CAP / 128, NEXP), 128, smem>>>(mask, out);

    combine_kernel<<<T_TOK, 256>>>(mask, out);
}

// round 9
// speedup vs baseline: 1.1370x; 1.0092x over previous
#include <cuda_runtime.h>
#include <cuda_bf16.h>
#include <cstdint>

// ---------------- problem constants ----------------
#define T_TOK   8192
#define D_MODEL 1024
#define D_COND  256
#define D_IN    1280      // D_MODEL + D_COND
#define D_FF    4096
#define NEXP    8
#define TOPK    2
#define CAP     2560      // int(1.25 * 2 * 8192 / 8)
#define TKA     (T_TOK*TOPK)

// ---------------- device scratch (static, no runtime allocation) ----------------
__device__ int   g_expert[TKA];
__device__ float g_weight[TKA];
__device__ int   g_slot[TKA];
__device__ int   g_route[NEXP*CAP];
__device__ int   g_cnt[NEXP];
__device__ float g_xc[(size_t)T_TOK * D_IN];            // tf32-rounded [x|cond]
__device__ float g_Hs[(size_t)T_TOK * D_FF];            // shared hidden (tf32-rounded)
__device__ float g_He[(size_t)NEXP * CAP * D_FF];       // expert hidden (tf32-rounded)
__device__ float g_Y [(size_t)NEXP * CAP * D_MODEL];    // expert output (fp32)
__device__ float g_W1sR[(size_t)D_IN * D_FF];           // tf32-rounded weight copies
__device__ float g_W2sR[(size_t)D_FF * D_MODEL];
__device__ float g_W1eR[(size_t)NEXP * D_IN * D_FF];
__device__ float g_W2eR[(size_t)NEXP * D_FF * D_MODEL];

// ---------------- helpers ----------------
__device__ __forceinline__ unsigned f2tf(float f) {
    unsigned u;
    asm("cvt.rna.tf32.f32 %0, %1;" : "=r"(u) : "f"(f));
    return u;
}
__device__ __forceinline__ float rtf(float f) { return __uint_as_float(f2tf(f)); }
__device__ __forceinline__ void cp16(void* dst_smem, const void* src_gmem) {
    unsigned sa = (unsigned)__cvta_generic_to_shared(dst_smem);
    asm volatile("cp.async.cg.shared.global [%0], [%1], 16;" :: "r"(sa), "l"(src_gmem));
}
__device__ __forceinline__ float gelu_f(float v) {
    // jax.nn.gelu (tanh form), HW tanh.approx
    float u = 0.7978845608028654f * (v + 0.044715f * v * v * v);
    float t;
    asm("tanh.approx.f32 %0, %1;" : "=f"(t) : "f"(u));
    return 0.5f * v * (1.0f + t);
}

// ---------------- 0a) pack + tf32-round [x|cond] ----------------
__global__ __launch_bounds__(256) void pack_round_kernel(const float* __restrict__ x,
                                                         const float* __restrict__ cond) {
    int i = blockIdx.x * 256 + threadIdx.x;        // float4 index; rows have 320 float4
    int t = i / 320, c4 = i % 320;
    float4 v;
    if (c4 < 256) v = ((const float4*)x)[(size_t)t * 256 + c4];
    else          v = ((const float4*)cond)[(size_t)t * 64 + (c4 - 256)];
    v.x = rtf(v.x); v.y = rtf(v.y); v.z = rtf(v.z); v.w = rtf(v.w);
    ((float4*)g_xc)[(size_t)t * 320 + c4] = v;
}

// ---------------- 0b) tf32-round copy (same layout) ----------------
__global__ __launch_bounds__(256) void round_copy_kernel(const float* __restrict__ src,
                                                         float* __restrict__ dst) {
    size_t i = (size_t)blockIdx.x * 256 + threadIdx.x;   // float4 index
    float4 v = ((const float4*)src)[i];
    v.x = rtf(v.x); v.y = rtf(v.y); v.z = rtf(v.z); v.w = rtf(v.w);
    ((float4*)dst)[i] = v;
}

// ---------------- 1) router ----------------
__global__ __launch_bounds__(256) void router_kernel(const float* __restrict__ x,
                                                     const float* __restrict__ Wr) {
    __shared__ float sWr[D_MODEL * NEXP];
    const int tid = threadIdx.x;
    for (int i = tid; i < D_MODEL * NEXP; i += 256) sWr[i] = Wr[i];
    __syncthreads();

    const int warp = tid >> 5, lane = tid & 31;
    const int t = blockIdx.x * 8 + warp;
    const float* xr = x + (size_t)t * D_MODEL;

    float acc[NEXP];
#pragma unroll
    for (int e = 0; e < NEXP; e++) acc[e] = 0.f;
    for (int j = lane; j < D_MODEL; j += 32) {
        float xv = xr[j];
        const float* wrow = sWr + j * NEXP;
#pragma unroll
        for (int e = 0; e < NEXP; e++) acc[e] += xv * wrow[e];
    }
#pragma unroll
    for (int e = 0; e < NEXP; e++)
#pragma unroll
        for (int o = 16; o > 0; o >>= 1) acc[e] += __shfl_xor_sync(0xffffffffu, acc[e], o);

    if (lane == 0) {
        float mx = acc[0];
#pragma unroll
        for (int e = 1; e < NEXP; e++) mx = fmaxf(mx, acc[e]);
        float p[NEXP];
#pragma unroll
        for (int e = 0; e < NEXP; e++) p[e] = expf(acc[e] - mx);
        int i1 = 0; float v1 = p[0];
#pragma unroll
        for (int e = 1; e < NEXP; e++) if (p[e] > v1) { v1 = p[e]; i1 = e; }
        int i2 = -1; float v2 = -1.f;
#pragma unroll
        for (int e = 0; e < NEXP; e++) if (e != i1 && p[e] > v2) { v2 = p[e]; i2 = e; }
        float inv = 1.f / (v1 + v2);   // softmax denom cancels in normalization
        g_expert[2 * t]     = i1;  g_weight[2 * t]     = v1 * inv;
        g_expert[2 * t + 1] = i2;  g_weight[2 * t + 1] = v2 * inv;
    }
}

// ---------------- 2) binning: deterministic stable per-expert ranks ----------------
__global__ __launch_bounds__(512) void binning_kernel() {
    __shared__ int scnt[512 * NEXP];
    const int tid = threadIdx.x;
    for (int i = tid; i < NEXP * CAP; i += 512) g_route[i] = 0;

    const int base = tid * (TKA / 512);
    int loc[NEXP];
#pragma unroll
    for (int e = 0; e < NEXP; e++) loc[e] = 0;
    for (int i = 0; i < TKA / 512; i++) loc[g_expert[base + i]]++;
#pragma unroll
    for (int e = 0; e < NEXP; e++) scnt[tid * NEXP + e] = loc[e];
    __syncthreads();

    if (tid < NEXP) {
        int run = 0;
        for (int i = 0; i < 512; i++) {
            int v = scnt[i * NEXP + tid];
            scnt[i * NEXP + tid] = run;
            run += v;
        }
        g_cnt[tid] = min(run, CAP);
    }
    __syncthreads();

    int offs[NEXP];
#pragma unroll
    for (int e = 0; e < NEXP; e++) offs[e] = scnt[tid * NEXP + e];
    for (int i = 0; i < TKA / 512; i++) {
        int a = base + i;
        int e = g_expert[a];
        int pos = offs[e]++;
        if (pos < CAP) {
            int slot = e * CAP + pos;
            g_route[slot] = a >> 1;
            g_slot[a] = slot;
        } else {
            g_slot[a] = -1;
        }
    }
}

// ---------------- 3) merged tiled tf32 GEMM: shared + expert tiles in one grid ----------------
// L1=true : y<64 -> g_Hs = rtf(gelu(g_xc @ W1s)) ; y>=64 -> g_He = rtf(gelu(gather @ W1e))
//           K=1280, N=4096
// L1=false: y<64 -> out = mask/3 * (g_Hs @ W2s)  ; y>=64 -> g_Y = g_He @ W2e
//           K=4096, N=1024
// 128x128 CTA tile, 4 warps (64x64 warp tile), 3-stage cp.async, 1 syncthreads/k-tile.
#define STAGES 3
template <bool L1>
__global__ __launch_bounds__(128, 2) void gemm_kernel(const float* __restrict__ mask,
                                                      float* __restrict__ out) {
    constexpr int BM = 128, BN = 128, BK = 32;
    constexpr int KDIM = L1 ? D_IN : D_FF;
    constexpr int NDIM = L1 ? D_FF : D_MODEL;
    constexpr int KT   = KDIM / BK;
    constexpr int ASTR = BK + 4;     // 36 floats
    constexpr int BSTR = BN + 8;     // 136 floats
    constexpr int ASZ  = BM * ASTR;  // 4608
    constexpr int BSZ  = BK * BSTR;  // 4352

    extern __shared__ float smem[];
    float* As = smem;                    // STAGES stages
    float* Bs = smem + STAGES * ASZ;

    const int tid = threadIdx.x;
    const int n0 = blockIdx.x * BN;

    // ---- y-decode: shared tiles first, then expert tiles ----
    const int y = blockIdx.y;
    const bool sh = (y < 64);
    int e = 0, m0;
    if (sh) {
        m0 = y * BM;
    } else {
        int t = y - 64;
        e = t / 20;                      // 20 M-tiles per expert (CAP/128)
        m0 = (t % 20) * BM;
        if (m0 >= g_cnt[e]) return;      // uniform skip of empty tiles
    }

    const float* Ab;
    const float* Wp;
    if (L1) {
        Ab = g_xc;
        Wp = sh ? g_W1sR : (g_W1eR + (size_t)e * D_IN * D_FF);
    } else {
        Ab = sh ? g_Hs : (g_He + (size_t)e * CAP * D_FF);
        Wp = sh ? g_W2sR : (g_W2eR + (size_t)e * D_FF * D_MODEL);
    }

    // ---- loader geometry (128 threads): A 128x32 (8 cp16/thr), B 32x128 (8 cp16/thr) ----
    const int a_cc = tid & 7;
    const int a_r0 = tid >> 3;
    const int b_cc = tid & 31;
    const int b_k0 = tid >> 5;

    const float* aptr[8];
#pragma unroll
    for (int i = 0; i < 8; i++) {
        int r = m0 + a_r0 + 16 * i;
        int row = (L1 && !sh) ? g_route[e * CAP + r] : r;
        aptr[i] = Ab + (size_t)row * KDIM + a_cc * 4;
    }

    auto load_tile = [&](int kt, int st) {
        const int k0 = kt * BK;
        float* as = As + st * ASZ;
        float* bs = Bs + st * BSZ;
#pragma unroll
        for (int i = 0; i < 8; i++)
            cp16(as + (a_r0 + 16 * i) * ASTR + a_cc * 4, aptr[i] + k0);
#pragma unroll
        for (int i = 0; i < 8; i++) {
            int kk = b_k0 + 4 * i;
            cp16(bs + kk * BSTR + b_cc * 4, Wp + (size_t)(k0 + kk) * NDIM + n0 + b_cc * 4);
        }
        asm volatile("cp.async.commit_group;" ::: "memory");
    };

    const int warp = tid >> 5, lane = tid & 31;
    const int wm = warp >> 1, wn = warp & 1;   // 2x2 warp grid; warp tile 64x64
    const int lr = lane >> 2, lc = lane & 3;

    float acc[4][8][4];
#pragma unroll
    for (int f = 0; f < 4; f++)
#pragma unroll
        for (int g = 0; g < 8; g++)
#pragma unroll
            for (int c = 0; c < 4; c++) acc[f][g][c] = 0.f;

    load_tile(0, 0);
    load_tile(1, 1);

    int cur = 0, nxt = 2;                  // slot of tile kt; slot for tile kt+2
    for (int kt = 0; kt < KT; kt++) {
        if (kt + 1 < KT) {
            asm volatile("cp.async.wait_group 1;" ::: "memory");
        } else {
            asm volatile("cp.async.wait_group 0;" ::: "memory");
        }
        __syncthreads();                   // tile kt visible; slot `nxt` fully drained
        if (kt + 2 < KT) load_tile(kt + 2, nxt);

        const float* as = As + cur * ASZ + (wm * 64 + lr) * ASTR + lc;
        const float* bs = Bs + cur * BSZ + wn * 64 + lr;
#pragma unroll
        for (int ks = 0; ks < 4; ks++) {
            const int kb = ks * 8;
            unsigned af[4][4], bf[8][2];
#pragma unroll
            for (int f = 0; f < 4; f++) {
                const float* p = as + f * 16 * ASTR + kb;
                af[f][0] = __float_as_uint(p[0]);
                af[f][1] = __float_as_uint(p[8 * ASTR]);
                af[f][2] = __float_as_uint(p[4]);
                af[f][3] = __float_as_uint(p[8 * ASTR + 4]);
            }
#pragma unroll
            for (int g = 0; g < 8; g++) {
                const float* p = bs + (kb + lc) * BSTR + g * 8;
                bf[g][0] = __float_as_uint(p[0]);
                bf[g][1] = __float_as_uint(p[4 * BSTR]);
            }
#pragma unroll
            for (int f = 0; f < 4; f++)
#pragma unroll
                for (int g = 0; g < 8; g++) {
                    asm volatile(
                        "mma.sync.aligned.m16n8k8.row.col.f32.tf32.tf32.f32 "
                        "{%0,%1,%2,%3}, {%4,%5,%6,%7}, {%8,%9}, {%0,%1,%2,%3};"
                        : "+f"(acc[f][g][0]), "+f"(acc[f][g][1]),
                          "+f"(acc[f][g][2]), "+f"(acc[f][g][3])
                        : "r"(af[f][0]), "r"(af[f][1]), "r"(af[f][2]), "r"(af[f][3]),
                          "r"(bf[g][0]), "r"(bf[g][1]));
                }
        }
        cur = (cur == STAGES - 1) ? 0 : cur + 1;
        nxt = (nxt == STAGES - 1) ? 0 : nxt + 1;
    }

    // ---- epilogue ----
#pragma unroll
    for (int f = 0; f < 4; f++) {
        const int row = m0 + wm * 64 + f * 16 + lr;   // +8 for c2/c3
#pragma unroll
        for (int g = 0; g < 8; g++) {
            const int col = n0 + wn * 64 + g * 8 + 2 * lc;
            if (L1) {
                float* dst = sh ? (g_Hs + (size_t)row * D_FF)
                                : (g_He + ((size_t)e * CAP + row) * D_FF);
                float2 v0 = make_float2(rtf(gelu_f(acc[f][g][0])), rtf(gelu_f(acc[f][g][1])));
                float2 v1 = make_float2(rtf(gelu_f(acc[f][g][2])), rtf(gelu_f(acc[f][g][3])));
                *(float2*)(dst + col) = v0;
                *(float2*)(dst + (size_t)8 * D_FF + col) = v1;
            } else if (sh) {
                float mk0 = mask[row] * (1.f / 3.f);
                float mk1 = mask[row + 8] * (1.f / 3.f);
                float2 v0 = make_float2(acc[f][g][0] * mk0, acc[f][g][1] * mk0);
                float2 v1 = make_float2(acc[f][g][2] * mk1, acc[f][g][3] * mk1);
                *(float2*)(out + (size_t)row * D_MODEL + col) = v0;
                *(float2*)(out + (size_t)(row + 8) * D_MODEL + col) = v1;
            } else {
                float* dst = g_Y + ((size_t)e * CAP + row) * D_MODEL;
                *(float2*)(dst + col) = make_float2(acc[f][g][0], acc[f][g][1]);
                *(float2*)(dst + (size_t)8 * D_MODEL + col) = make_float2(acc[f][g][2], acc[f][g][3]);
            }
        }
    }
}

// ---------------- 4) combine: out += (2/3)*mask*(w0*Y[s0] + w1*Y[s1]) ----------------
__global__ __launch_bounds__(256) void combine_kernel(const float* __restrict__ mask,
                                                      float* __restrict__ out) {
    const int idx = blockIdx.x * 256 + threadIdx.x;
    const int t = idx >> 8;
    const int c = (idx & 255) * 4;
    const int s0 = g_slot[2 * t], s1 = g_slot[2 * t + 1];
    const float w0 = g_weight[2 * t], w1 = g_weight[2 * t + 1];
    const float m = mask[t] * (2.f / 3.f);
    float ax = 0.f, ay = 0.f, az = 0.f, aw = 0.f;
    if (s0 >= 0) {
        float4 y = *(const float4*)(g_Y + (size_t)s0 * D_MODEL + c);
        ax += w0 * y.x; ay += w0 * y.y; az += w0 * y.z; aw += w0 * y.w;
    }
    if (s1 >= 0) {
        float4 y = *(const float4*)(g_Y + (size_t)s1 * D_MODEL + c);
        ax += w1 * y.x; ay += w1 * y.y; az += w1 * y.z; aw += w1 * y.w;
    }
    float4 o = *(float4*)(out + (size_t)t * D_MODEL + c);
    o.x += m * ax; o.y += m * ay; o.z += m * az; o.w += m * aw;
    *(float4*)(out + (size_t)t * D_MODEL + c) = o;
}

// ---------------- launch ----------------
extern "C" void kernel_launch(void* const* d_in, const int* in_sizes, int n_in,
                              void* d_out, int out_size) {
    const float* x    = (const float*)d_in[0];
    const float* cond = (const float*)d_in[1];
    const float* mask = (const float*)d_in[2];
    const float* Wr   = (const float*)d_in[3];
    const float* W1s  = (const float*)d_in[4];
    const float* W2s  = (const float*)d_in[5];
    const float* W1e  = (const float*)d_in[6];
    const float* W2e  = (const float*)d_in[7];
    float* out = (float*)d_out;

    const int smem = STAGES * (128 * 36 + 32 * 136) * (int)sizeof(float);  // 107520 B
    cudaFuncSetAttribute(gemm_kernel<true>,  cudaFuncAttributeMaxDynamicSharedMemorySize, smem);
    cudaFuncSetAttribute(gemm_kernel<false>, cudaFuncAttributeMaxDynamicSharedMemorySize, smem);

    float* w1s; cudaGetSymbolAddress((void**)&w1s, g_W1sR);
    float* w2s; cudaGetSymbolAddress((void**)&w2s, g_W2sR);
    float* w1e; cudaGetSymbolAddress((void**)&w1e, g_W1eR);
    float* w2e; cudaGetSymbolAddress((void**)&w2e, g_W2eR);

    // pre-round all GEMM operands to tf32 (rna), once
    pack_round_kernel<<<T_TOK * 320 / 256, 256>>>(x, cond);
    round_copy_kernel<<<(D_IN * D_FF) / 1024, 256>>>(W1s, w1s);
    round_copy_kernel<<<(D_FF * D_MODEL) / 1024, 256>>>(W2s, w2s);
    round_copy_kernel<<<(NEXP * D_IN * D_FF) / 1024, 256>>>(W1e, w1e);
    round_copy_kernel<<<(NEXP * D_FF * D_MODEL) / 1024, 256>>>(W2e, w2e);

    router_kernel<<<T_TOK / 8, 256>>>(x, Wr);
    binning_kernel<<<1, 512>>>();

    // merged GEMMs: y = 64 shared tiles + 8*20 expert tiles = 224
    gemm_kernel<true><<<dim3(D_FF / 128, 224),    128, smem>>>(mask, out);
    gemm_kernel<false><<<dim3(D_MODEL / 128, 224), 128, smem>>>(mask, out);

    combine_kernel<<<T_TOK, 256>>>(mask, out);
}